// round 1
// baseline (speedup 1.0000x reference)
#include <cuda_runtime.h>

#define NCLS 14
#define MAXP 32
#define MAXN 64
#define PREF 16   // prefetched chunks of 32 rows => 512 rows fast path

__global__ __launch_bounds__(NCLS * 32)
void pauc_kernel(const float* __restrict__ logits,
                 const int*   __restrict__ targets,
                 float* __restrict__ out,
                 int Bn) {
    __shared__ float pos_buf[NCLS][MAXP];
    __shared__ float neg_buf[NCLS][MAXN];
    __shared__ float cls_loss[NCLS];
    __shared__ int   cls_active[NCLS];

    const int w    = threadIdx.x >> 5;   // warp == class
    const int lane = threadIdx.x & 31;

    if (w < NCLS) {
        const int c = w;
        int npos = 0, nneg = 0;
        const unsigned below = (1u << lane) - 1u;

        // ---- fast path: speculative 512-row prefetch (MLP=16) ----
        int   tv[PREF];
        float lv[PREF];
#pragma unroll
        for (int k = 0; k < PREF; k++) {
            long long row = (long long)k * 32 + lane;
            if (row < Bn) {
                tv[k] = targets[row * NCLS + c];
                lv[k] = logits [row * NCLS + c];
            } else {
                tv[k] = -1; lv[k] = 0.f;
            }
        }
#pragma unroll
        for (int k = 0; k < PREF; k++) {
            unsigned pm = __ballot_sync(0xffffffffu, tv[k] == 1);
            unsigned nm = __ballot_sync(0xffffffffu, tv[k] == 0);
            if (tv[k] == 1) {
                int r = npos + __popc(pm & below);
                if (r < MAXP) pos_buf[c][r] = lv[k];
            }
            if (tv[k] == 0) {
                int r = nneg + __popc(nm & below);
                if (r < MAXN) neg_buf[c][r] = lv[k];
            }
            npos += __popc(pm);
            nneg += __popc(nm);
        }

        // ---- slow path: continue scan only if buffers not full ----
        long long base = (long long)PREF * 32;
        while ((npos < MAXP || nneg < MAXN) && base < Bn) {
            long long row = base + lane;
            int t = -1; float l = 0.f;
            if (row < Bn) {
                t = targets[row * NCLS + c];
                l = logits [row * NCLS + c];
            }
            unsigned pm = __ballot_sync(0xffffffffu, t == 1);
            unsigned nm = __ballot_sync(0xffffffffu, t == 0);
            if (t == 1) {
                int r = npos + __popc(pm & below);
                if (r < MAXP) pos_buf[c][r] = l;
            }
            if (t == 0) {
                int r = nneg + __popc(nm & below);
                if (r < MAXN) neg_buf[c][r] = l;
            }
            npos += __popc(pm);
            nneg += __popc(nm);
            base += 32;
        }

        const int tp = min(npos, MAXP);
        const int tn = min(nneg, MAXN);
        __syncwarp();

        // ---- pairwise softplus loss over tp x tn pairs ----
        float s = 0.f;
        const int total = tp * tn;
        for (int idx = lane; idx < total; idx += 32) {
            int i = idx / tn;
            int j = idx - i * tn;
            float x = neg_buf[c][j] - pos_buf[c][i];        // = -(pos-neg-MARGIN), MARGIN=0
            s += fmaxf(x, 0.f) + log1pf(__expf(-fabsf(x))); // softplus(x), logaddexp form
        }
#pragma unroll
        for (int off = 16; off; off >>= 1)
            s += __shfl_down_sync(0xffffffffu, s, off);

        if (lane == 0) {
            bool act = (tp > 0) && (tn > 0);
            cls_loss[c]   = act ? s / (float)max(total, 1) : 0.f;
            cls_active[c] = act ? 1 : 0;
        }
    }
    __syncthreads();

    if (threadIdx.x == 0) {
        float ls = 0.f; int cnt = 0;
#pragma unroll
        for (int c = 0; c < NCLS; c++) { ls += cls_loss[c]; cnt += cls_active[c]; }
        out[0] = (cnt > 0) ? ls / (float)cnt : 0.f;
    }
}

extern "C" void kernel_launch(void* const* d_in, const int* in_sizes, int n_in,
                              void* d_out, int out_size) {
    const float* logits  = (const float*)d_in[0];
    const int*   targets = (const int*)  d_in[1];
    float*       out     = (float*)d_out;
    int Bn = in_sizes[0] / NCLS;
    pauc_kernel<<<1, NCLS * 32>>>(logits, targets, out, Bn);
}

// round 2
// speedup vs baseline: 1.3528x; 1.3528x over previous
#include <cuda_runtime.h>

#define NCLS 14
#define MAXP 32
#define MAXN 64
#define PREF 16      // 512-row speculative fast path
#define TPB  256     // 8 warps per block

__device__ float    g_cls_loss[NCLS];
__device__ int      g_cls_active[NCLS];
__device__ unsigned g_ticket;   // zero-init; wraps mod NCLS across graph replays

__global__ __launch_bounds__(TPB)
void pauc_kernel(const float* __restrict__ logits,
                 const int*   __restrict__ targets,
                 float* __restrict__ out,
                 int Bn) {
    __shared__ float pos_buf[MAXP];
    __shared__ float neg_buf[MAXN];
    __shared__ int   s_tp, s_tn;
    __shared__ float warp_sum[TPB / 32];

    const int c    = blockIdx.x;          // class
    const int tid  = threadIdx.x;
    const int w    = tid >> 5;
    const int lane = tid & 31;

    // ---- phase 1: warp 0 scans for first MAXP positives / MAXN negatives ----
    if (w == 0) {
        int npos = 0, nneg = 0;
        const unsigned below = (1u << lane) - 1u;

        int   tv[PREF];
        float lv[PREF];
#pragma unroll
        for (int k = 0; k < PREF; k++) {
            long long row = (long long)k * 32 + lane;
            if (row < Bn) {
                tv[k] = targets[row * NCLS + c];
                lv[k] = logits [row * NCLS + c];
            } else { tv[k] = -1; lv[k] = 0.f; }
        }
#pragma unroll
        for (int k = 0; k < PREF; k++) {
            unsigned pm = __ballot_sync(0xffffffffu, tv[k] == 1);
            unsigned nm = __ballot_sync(0xffffffffu, tv[k] == 0);
            if (tv[k] == 1) {
                int r = npos + __popc(pm & below);
                if (r < MAXP) pos_buf[r] = lv[k];
            }
            if (tv[k] == 0) {
                int r = nneg + __popc(nm & below);
                if (r < MAXN) neg_buf[r] = lv[k];
            }
            npos += __popc(pm);
            nneg += __popc(nm);
        }

        // slow path (statistically never taken; required for correctness)
        long long base = (long long)PREF * 32;
        while ((npos < MAXP || nneg < MAXN) && base < Bn) {
            long long row = base + lane;
            int t = -1; float l = 0.f;
            if (row < Bn) {
                t = targets[row * NCLS + c];
                l = logits [row * NCLS + c];
            }
            unsigned pm = __ballot_sync(0xffffffffu, t == 1);
            unsigned nm = __ballot_sync(0xffffffffu, t == 0);
            if (t == 1) {
                int r = npos + __popc(pm & below);
                if (r < MAXP) pos_buf[r] = l;
            }
            if (t == 0) {
                int r = nneg + __popc(nm & below);
                if (r < MAXN) neg_buf[r] = l;
            }
            npos += __popc(pm);
            nneg += __popc(nm);
            base += 32;
        }
        if (lane == 0) { s_tp = min(npos, MAXP); s_tn = min(nneg, MAXN); }
    }
    __syncthreads();

    const int tp = s_tp, tn = s_tn;

    // ---- phase 2: all 8 warps share the tp x tn pair loss ----
    float s = 0.f;
    if (tp == MAXP && tn == MAXN) {
        // common case: 2048 pairs, 8 per thread, shift/mask indexing
#pragma unroll
        for (int u = 0; u < (MAXP * MAXN) / TPB; u++) {
            int idx = tid + u * TPB;
            float x = neg_buf[idx & (MAXN - 1)] - pos_buf[idx >> 6];
            s += fmaxf(x, 0.f) + log1pf(__expf(-fabsf(x)));
        }
    } else {
        const int total = tp * tn;
        for (int idx = tid; idx < total; idx += TPB) {
            int i = idx / tn;
            int j = idx - i * tn;
            float x = neg_buf[j] - pos_buf[i];
            s += fmaxf(x, 0.f) + log1pf(__expf(-fabsf(x)));
        }
    }
#pragma unroll
    for (int off = 16; off; off >>= 1)
        s += __shfl_down_sync(0xffffffffu, s, off);
    if (lane == 0) warp_sum[w] = s;
    __syncthreads();

    // ---- phase 3: block finalize, then last-block global mean ----
    if (tid == 0) {
        float bs = 0.f;
#pragma unroll
        for (int i = 0; i < TPB / 32; i++) bs += warp_sum[i];
        bool act = (tp > 0) && (tn > 0);
        g_cls_loss[c]   = act ? bs / (float)max(tp * tn, 1) : 0.f;
        g_cls_active[c] = act ? 1 : 0;
        __threadfence();
        unsigned ticket = atomicAdd(&g_ticket, 1u);
        if (ticket % NCLS == NCLS - 1) {          // last block of this launch
            __threadfence();
            float ls = 0.f; int cnt = 0;
#pragma unroll
            for (int k = 0; k < NCLS; k++) { ls += g_cls_loss[k]; cnt += g_cls_active[k]; }
            out[0] = (cnt > 0) ? ls / (float)cnt : 0.f;
        }
    }
}

extern "C" void kernel_launch(void* const* d_in, const int* in_sizes, int n_in,
                              void* d_out, int out_size) {
    const float* logits  = (const float*)d_in[0];
    const int*   targets = (const int*)  d_in[1];
    float*       out     = (float*)d_out;
    int Bn = in_sizes[0] / NCLS;
    pauc_kernel<<<NCLS, TPB>>>(logits, targets, out, Bn);
}

// round 3
// speedup vs baseline: 1.7059x; 1.2610x over previous
#include <cuda_runtime.h>

#define NCLS 14
#define MAXP 32
#define MAXN 64
#define PREF 9       // 288-row speculative fast path (mean 96 pos/neg, 8 sigma margin)
#define TPB  256     // 8 warps per block

__device__ float    g_cls_loss[NCLS];
__device__ int      g_cls_active[NCLS];
__device__ unsigned g_ticket;   // atomicInc-wrapped mod NCLS across graph replays

// branch-free softplus(x) = max(x,0) + log(1 + exp(-|x|)); MUFU only
__device__ __forceinline__ float softplus_fast(float x) {
    return fmaxf(x, 0.f) + __logf(1.f + __expf(-fabsf(x)));
}

__global__ __launch_bounds__(TPB)
void pauc_kernel(const float* __restrict__ logits,
                 const int*   __restrict__ targets,
                 float* __restrict__ out,
                 int Bn) {
    __shared__ float pos_buf[MAXP];
    __shared__ float neg_buf[MAXN];
    __shared__ int   s_tp, s_tn;
    __shared__ float warp_sum[TPB / 32];

    const int c    = blockIdx.x;          // class
    const int tid  = threadIdx.x;
    const int w    = tid >> 5;
    const int lane = tid & 31;

    // ---- phase 1: warp 0 scans for first MAXP positives / MAXN negatives ----
    if (w == 0) {
        int npos = 0, nneg = 0;
        const unsigned below = (1u << lane) - 1u;

        int   tv[PREF];
        float lv[PREF];
#pragma unroll
        for (int k = 0; k < PREF; k++) {
            int row = k * 32 + lane;
            if (row < Bn) {
                tv[k] = targets[row * NCLS + c];
                lv[k] = logits [row * NCLS + c];
            } else { tv[k] = -1; lv[k] = 0.f; }
        }
#pragma unroll
        for (int k = 0; k < PREF; k++) {
            unsigned pm = __ballot_sync(0xffffffffu, tv[k] == 1);
            unsigned nm = __ballot_sync(0xffffffffu, tv[k] == 0);
            if (tv[k] == 1) {
                int r = npos + __popc(pm & below);
                if (r < MAXP) pos_buf[r] = lv[k];
            }
            if (tv[k] == 0) {
                int r = nneg + __popc(nm & below);
                if (r < MAXN) neg_buf[r] = lv[k];
            }
            npos += __popc(pm);
            nneg += __popc(nm);
        }

        // slow path (statistically never taken; required for exactness)
        int base = PREF * 32;
        while ((npos < MAXP || nneg < MAXN) && base < Bn) {
            int row = base + lane;
            int t = -1; float l = 0.f;
            if (row < Bn) {
                t = targets[row * NCLS + c];
                l = logits [row * NCLS + c];
            }
            unsigned pm = __ballot_sync(0xffffffffu, t == 1);
            unsigned nm = __ballot_sync(0xffffffffu, t == 0);
            if (t == 1) {
                int r = npos + __popc(pm & below);
                if (r < MAXP) pos_buf[r] = l;
            }
            if (t == 0) {
                int r = nneg + __popc(nm & below);
                if (r < MAXN) neg_buf[r] = l;
            }
            npos += __popc(pm);
            nneg += __popc(nm);
            base += 32;
        }
        if (lane == 0) { s_tp = min(npos, MAXP); s_tn = min(nneg, MAXN); }
    }
    __syncthreads();

    const int tp = s_tp, tn = s_tn;

    // ---- phase 2: all 8 warps share the tp x tn pair loss ----
    float s = 0.f;
    if (tp == MAXP && tn == MAXN) {
        // common case: 2048 pairs, 8 per thread, shift/mask indexing
#pragma unroll
        for (int u = 0; u < (MAXP * MAXN) / TPB; u++) {
            int idx = tid + u * TPB;
            s += softplus_fast(neg_buf[idx & (MAXN - 1)] - pos_buf[idx >> 6]);
        }
    } else {
        const int total = tp * tn;
        for (int idx = tid; idx < total; idx += TPB) {
            int i = idx / tn;
            int j = idx - i * tn;
            s += softplus_fast(neg_buf[j] - pos_buf[i]);
        }
    }
#pragma unroll
    for (int off = 16; off; off >>= 1)
        s += __shfl_xor_sync(0xffffffffu, s, off);
    if (lane == 0) warp_sum[w] = s;
    __syncthreads();

    // ---- phase 3: block finalize, then last-block global mean ----
    if (tid == 0) {
        float bs = 0.f;
#pragma unroll
        for (int i = 0; i < TPB / 32; i++) bs += warp_sum[i];
        bool act = (tp > 0) && (tn > 0);
        g_cls_loss[c]   = act ? bs / (float)max(tp * tn, 1) : 0.f;
        g_cls_active[c] = act ? 1 : 0;
        __threadfence();
        unsigned ticket = atomicInc(&g_ticket, NCLS - 1u);   // wraps 13 -> 0
        if (ticket == NCLS - 1u) {                           // last block this launch
            __threadfence();
            float ls = 0.f; int cnt = 0;
#pragma unroll
            for (int k = 0; k < NCLS; k++) { ls += g_cls_loss[k]; cnt += g_cls_active[k]; }
            out[0] = (cnt > 0) ? ls / (float)cnt : 0.f;
        }
    }
}

extern "C" void kernel_launch(void* const* d_in, const int* in_sizes, int n_in,
                              void* d_out, int out_size) {
    const float* logits  = (const float*)d_in[0];
    const int*   targets = (const int*)  d_in[1];
    float*       out     = (float*)d_out;
    int Bn = in_sizes[0] / NCLS;
    pauc_kernel<<<NCLS, TPB>>>(logits, targets, out, Bn);
}